// round 5
// baseline (speedup 1.0000x reference)
#include <cuda_runtime.h>
#include <cuda_fp16.h>
#include <math.h>
#include <stdint.h>

#define NN 50000
#define EE 800000
#define DD 64
#define BR 128   // rows per GEMM block
#define CAP 96   // per-warp smem edge stash (max degree safety: Poisson(16))

// ---------------- device scratch (static, no allocation) ----------------
__device__ int   g_flag;                 // 1 if edge_index is int64
__device__ int   g_cnt[NN];
__device__ int   g_rowptr[NN + 1];
__device__ int   g_fill[NN];
__device__ unsigned short g_srcs16[EE];  // src ids sorted by dst (CSR)
__device__ __align__(16) float  g_buf[NN * DD];    // layer activation (fp32)
__device__ __align__(16) __half g_hh[NN * DD];     // per-conv h (fp16)
__device__ float g_ssrc[NN];
__device__ float g_sdst[NN];

// ---------------- detect dtype + zero counters (launch 0) ----------------
__global__ void k_detect_zero(const int* __restrict__ raw) {
    int i = blockIdx.x * blockDim.x + threadIdx.x;
    if (i < NN) g_cnt[i] = 0;
    if (blockIdx.x == 0) {
        __shared__ int ok;
        if (threadIdx.x == 0) ok = 1;
        __syncthreads();
        for (int j = threadIdx.x; j < 4096; j += blockDim.x)
            if (raw[2 * j + 1] != 0) ok = 0;
        __syncthreads();
        if (threadIdx.x == 0) g_flag = ok;
    }
}

// ---------------- histogram of dst, 4 edges/thread (launch 1) -----------
__global__ void k_hist(const void* __restrict__ raw, int E) {
    int base = (blockIdx.x * blockDim.x + threadIdx.x) * 4;
    if (g_flag) {
        const long long* p = (const long long*)raw + E;   // dst row
#pragma unroll
        for (int u = 0; u < 4; u++) {
            int j = base + u;
            if (j < E) atomicAdd(&g_cnt[(int)p[j]], 1);
        }
    } else {
        const int* p = (const int*)raw + E;
#pragma unroll
        for (int u = 0; u < 4; u++) {
            int j = base + u;
            if (j < E) atomicAdd(&g_cnt[p[j]], 1);
        }
    }
}

// ---------------- single-block scan (launch 2) ----------------
__global__ void k_scan() {
    const int T = 1024;
    const int CH = (NN + T - 1) / T;
    __shared__ int sh[T];
    int tid = threadIdx.x;
    int begin = tid * CH;
    int end = begin + CH; if (end > NN) end = NN;
    if (begin > NN) begin = NN;
    int s = 0;
    for (int i = begin; i < end; i++) s += g_cnt[i];
    sh[tid] = s;
    __syncthreads();
    for (int off = 1; off < T; off <<= 1) {
        int v = (tid >= off) ? sh[tid - off] : 0;
        __syncthreads();
        sh[tid] += v;
        __syncthreads();
    }
    int run = sh[tid] - s;
    for (int i = begin; i < end; i++) {
        g_rowptr[i] = run;
        g_fill[i] = run;
        run += g_cnt[i];
    }
    if (tid == T - 1) g_rowptr[NN] = sh[T - 1];
}

// ---------------- scatter into CSR, 4 edges/thread (launch 3) -----------
__global__ void k_scatter(const void* __restrict__ raw, int E) {
    int base = (blockIdx.x * blockDim.x + threadIdx.x) * 4;
    if (g_flag) {
        const long long* p = (const long long*)raw;
#pragma unroll
        for (int u = 0; u < 4; u++) {
            int j = base + u;
            if (j < E) {
                int s = (int)p[j], d = (int)p[E + j];
                int pos = atomicAdd(&g_fill[d], 1);
                g_srcs16[pos] = (unsigned short)s;
            }
        }
    } else {
        const int* p = (const int*)raw;
#pragma unroll
        for (int u = 0; u < 4; u++) {
            int j = base + u;
            if (j < E) {
                int s = p[j], d = p[E + j];
                int pos = atomicAdd(&g_fill[d], 1);
                g_srcs16[pos] = (unsigned short)s;
            }
        }
    }
}

// ---------------- register-tiled GEMM + fused score projections ----------
__global__ void __launch_bounds__(128) k_gemm(
        const float* __restrict__ xext, int use_ext,
        const float* __restrict__ W,
        const float* __restrict__ a_s,
        const float* __restrict__ a_d) {
    __shared__ float xs[DD][BR];
    __shared__ float ws[DD][DD];
    const float* x = use_ext ? xext : g_buf;
    int t = threadIdx.x;
    int rb = blockIdx.x * BR;

    {
        const float4* Wv = (const float4*)W;
        float4* wsv = (float4*)ws;
        for (int i = t; i < DD * DD / 4; i += 128) wsv[i] = Wv[i];
    }
    {
        int row = rb + t;
        int rs = (row < NN) ? row : 0;
        const float4* xr = (const float4*)(x + (size_t)rs * DD);
#pragma unroll
        for (int q = 0; q < 16; q++) {
            float4 v = xr[q];
            xs[q * 4 + 0][t] = v.x;
            xs[q * 4 + 1][t] = v.y;
            xs[q * 4 + 2][t] = v.z;
            xs[q * 4 + 3][t] = v.w;
        }
    }
    __syncthreads();

    int tx = t & 7, ty = t >> 3;
    float acc[8][8];
#pragma unroll
    for (int i = 0; i < 8; i++)
#pragma unroll
        for (int j = 0; j < 8; j++) acc[i][j] = 0.f;

    const float4* xs4 = (const float4*)xs;
    const float4* ws4 = (const float4*)ws;

#pragma unroll 8
    for (int k = 0; k < DD; k++) {
        float4 a0 = xs4[k * (BR / 4) + ty * 2];
        float4 a1 = xs4[k * (BR / 4) + ty * 2 + 1];
        float4 b0 = ws4[k * (DD / 4) + tx * 2];
        float4 b1 = ws4[k * (DD / 4) + tx * 2 + 1];
        float av[8] = {a0.x, a0.y, a0.z, a0.w, a1.x, a1.y, a1.z, a1.w};
        float bv[8] = {b0.x, b0.y, b0.z, b0.w, b1.x, b1.y, b1.z, b1.w};
#pragma unroll
        for (int i = 0; i < 8; i++)
#pragma unroll
            for (int j = 0; j < 8; j++)
                acc[i][j] = fmaf(av[i], bv[j], acc[i][j]);
    }

    float as[8], ad[8];
#pragma unroll
    for (int j = 0; j < 8; j++) {
        as[j] = a_s[tx * 8 + j];
        ad[j] = a_d[tx * 8 + j];
    }
    uint4* h16 = (uint4*)g_hh;
#pragma unroll
    for (int i = 0; i < 8; i++) {
        int row = rb + ty * 8 + i;
        float ss = 0.f, sd = 0.f;
#pragma unroll
        for (int j = 0; j < 8; j++) {
            ss = fmaf(acc[i][j], as[j], ss);
            sd = fmaf(acc[i][j], ad[j], sd);
        }
#pragma unroll
        for (int o = 4; o; o >>= 1) {
            ss += __shfl_xor_sync(0xffffffffu, ss, o);
            sd += __shfl_xor_sync(0xffffffffu, sd, o);
        }
        if (row < NN) {
            uint4 pk;
            *reinterpret_cast<__half2*>(&pk.x) = __floats2half2_rn(acc[i][0], acc[i][1]);
            *reinterpret_cast<__half2*>(&pk.y) = __floats2half2_rn(acc[i][2], acc[i][3]);
            *reinterpret_cast<__half2*>(&pk.z) = __floats2half2_rn(acc[i][4], acc[i][5]);
            *reinterpret_cast<__half2*>(&pk.w) = __floats2half2_rn(acc[i][6], acc[i][7]);
            h16[(size_t)row * 8 + tx] = pk;
            if (tx == 0) { g_ssrc[row] = ss; g_sdst[row] = sd; }
        }
    }
}

// ---------------- per-dst softmax + aggregation, smem edge stash --------
// One warp per dst node, 8 warps/block. Pass A gathers scores once and
// stashes (e, src) in smem; pass B has NO dependent global loads — only the
// independent coalesced h gather, which pipelines.
__global__ void __launch_bounds__(256) k_agg(float* __restrict__ yext,
                                             int use_ext, int do_elu) {
    __shared__ float se[8][CAP];
    __shared__ unsigned short ssrc_s[8][CAP];
    int wib = threadIdx.x >> 5;
    int w = (blockIdx.x * blockDim.x + threadIdx.x) >> 5;
    int lane = threadIdx.x & 31;
    if (w >= NN) return;
    float* y = use_ext ? yext : g_buf;
    int start = g_rowptr[w], end = g_rowptr[w + 1];
    float sd = g_sdst[w];

    // pass A: gather scores, stash, online max+sum
    float m = -1e30f, z = 0.f;
    for (int j = start + lane; j < end; j += 32) {
        unsigned short s = g_srcs16[j];
        float e = g_ssrc[s] + sd;
        e = (e > 0.f) ? e : 0.2f * e;
        int idx = j - start;
        if (idx < CAP) { se[wib][idx] = e; ssrc_s[wib][idx] = s; }
        if (e > m) { z *= __expf(m - e); m = e; }
        z += __expf(e - m);
    }
    float M = m;
#pragma unroll
    for (int o = 16; o; o >>= 1) M = fmaxf(M, __shfl_xor_sync(0xffffffffu, M, o));
    z *= __expf(m - M);
#pragma unroll
    for (int o = 16; o; o >>= 1) z += __shfl_xor_sync(0xffffffffu, z, o);
    float inv = 1.f / (z + 1e-16f);
    __syncwarp();

    // pass B: two half-warps, 2 edges/iter; e and s come from smem
    int half = lane >> 4, l16 = lane & 15;
    float4 acc = make_float4(0.f, 0.f, 0.f, 0.f);
    const uint2* h8 = (const uint2*)g_hh;
    for (int j = start + half; j < end; j += 2) {
        int idx = j - start;
        int s; float e;
        if (idx < CAP) {
            s = ssrc_s[wib][idx];
            e = se[wib][idx];
        } else {                       // overflow fallback (statistically never)
            s = g_srcs16[j];
            e = g_ssrc[s] + sd;
            e = (e > 0.f) ? e : 0.2f * e;
        }
        float wgt = __expf(e - M) * inv;
        uint2 hv = h8[(size_t)s * 16 + l16];
        float2 f0 = __half22float2(*reinterpret_cast<const __half2*>(&hv.x));
        float2 f1 = __half22float2(*reinterpret_cast<const __half2*>(&hv.y));
        acc.x = fmaf(f0.x, wgt, acc.x);
        acc.y = fmaf(f0.y, wgt, acc.y);
        acc.z = fmaf(f1.x, wgt, acc.z);
        acc.w = fmaf(f1.y, wgt, acc.w);
    }
    acc.x += __shfl_xor_sync(0xffffffffu, acc.x, 16);
    acc.y += __shfl_xor_sync(0xffffffffu, acc.y, 16);
    acc.z += __shfl_xor_sync(0xffffffffu, acc.z, 16);
    acc.w += __shfl_xor_sync(0xffffffffu, acc.w, 16);
    if (half == 0) {
        if (do_elu) {
            acc.x = (acc.x > 0.f) ? acc.x : (__expf(acc.x) - 1.f);
            acc.y = (acc.y > 0.f) ? acc.y : (__expf(acc.y) - 1.f);
            acc.z = (acc.z > 0.f) ? acc.z : (__expf(acc.z) - 1.f);
            acc.w = (acc.w > 0.f) ? acc.w : (__expf(acc.w) - 1.f);
        }
        ((float4*)y)[(size_t)w * 16 + l16] = acc;
    }
}

// ---------------- launch ----------------
extern "C" void kernel_launch(void* const* d_in, const int* in_sizes, int n_in,
                              void* d_out, int out_size) {
    const float* feat  = (const float*)d_in[0];
    const void*  eidx  = d_in[1];
    const float* W1    = (const float*)d_in[2];
    const float* a_s1  = (const float*)d_in[3];
    const float* a_d1  = (const float*)d_in[4];
    const float* W2    = (const float*)d_in[5];
    const float* a_s2  = (const float*)d_in[6];
    const float* a_d2  = (const float*)d_in[7];
    float* out = (float*)d_out;

    int E = in_sizes[1] / 2;

    k_detect_zero<<<(NN + 1023) / 1024, 1024>>>((const int*)eidx);
    k_hist<<<(E / 4 + 255) / 256, 256>>>(eidx, E);
    k_scan<<<1, 1024>>>();
    k_scatter<<<(E / 4 + 255) / 256, 256>>>(eidx, E);

    const int gemm_grid = (NN + BR - 1) / BR;
    const int agg_grid  = (NN * 32 + 255) / 256;

    for (int layer = 0; layer < 2; layer++) {
        const float* W  = layer ? W2   : W1;
        const float* as = layer ? a_s2 : a_s1;
        const float* ad = layer ? a_d2 : a_d1;
        for (int head = 0; head < 4; head++) {
            int first = (layer == 0 && head == 0);
            int last  = (layer == 1 && head == 3);
            int eol   = (head == 3);
            k_gemm<<<gemm_grid, 128>>>(feat, first, W + head * DD * DD,
                                       as + head * DD, ad + head * DD);
            k_agg<<<agg_grid, 256>>>(out, last, eol);
        }
    }
}

// round 6
// speedup vs baseline: 1.0542x; 1.0542x over previous
#include <cuda_runtime.h>
#include <cuda_fp16.h>
#include <cuda_bf16.h>
#include <math.h>
#include <stdint.h>

#define NN 50000
#define EE 800000
#define DD 64
#define BR 96    // rows per GEMM block (3 warps x 32 rows)

// ---------------- device scratch (static, no allocation) ----------------
__device__ int   g_flag;                 // 1 if edge_index is int64
__device__ int   g_cnt[NN];
__device__ int   g_rowptr[NN + 1];
__device__ int   g_fill[NN];
__device__ unsigned short g_srcs16[EE];  // src ids sorted by dst (CSR)
__device__ __align__(16) float  g_buf[NN * DD];    // layer activation (fp32)
__device__ __align__(16) __half g_hh[NN * DD];     // per-conv h (fp16)
__device__ float g_ssrc[NN];
__device__ float g_sdst[NN];

// ---------------- detect dtype + zero counters (launch 0) ----------------
__global__ void k_detect_zero(const int* __restrict__ raw) {
    int i = blockIdx.x * blockDim.x + threadIdx.x;
    if (i < NN) g_cnt[i] = 0;
    if (blockIdx.x == 0) {
        __shared__ int ok;
        if (threadIdx.x == 0) ok = 1;
        __syncthreads();
        for (int j = threadIdx.x; j < 4096; j += blockDim.x)
            if (raw[2 * j + 1] != 0) ok = 0;
        __syncthreads();
        if (threadIdx.x == 0) g_flag = ok;
    }
}

// ---------------- histogram of dst, 4 edges/thread (launch 1) -----------
__global__ void k_hist(const void* __restrict__ raw, int E) {
    int base = (blockIdx.x * blockDim.x + threadIdx.x) * 4;
    if (g_flag) {
        const long long* p = (const long long*)raw + E;
#pragma unroll
        for (int u = 0; u < 4; u++) {
            int j = base + u;
            if (j < E) atomicAdd(&g_cnt[(int)p[j]], 1);
        }
    } else {
        const int* p = (const int*)raw + E;
#pragma unroll
        for (int u = 0; u < 4; u++) {
            int j = base + u;
            if (j < E) atomicAdd(&g_cnt[p[j]], 1);
        }
    }
}

// ---------------- single-block scan (launch 2) ----------------
__global__ void k_scan() {
    const int T = 1024;
    const int CH = (NN + T - 1) / T;
    __shared__ int sh[T];
    int tid = threadIdx.x;
    int begin = tid * CH;
    int end = begin + CH; if (end > NN) end = NN;
    if (begin > NN) begin = NN;
    int s = 0;
    for (int i = begin; i < end; i++) s += g_cnt[i];
    sh[tid] = s;
    __syncthreads();
    for (int off = 1; off < T; off <<= 1) {
        int v = (tid >= off) ? sh[tid - off] : 0;
        __syncthreads();
        sh[tid] += v;
        __syncthreads();
    }
    int run = sh[tid] - s;
    for (int i = begin; i < end; i++) {
        g_rowptr[i] = run;
        g_fill[i] = run;
        run += g_cnt[i];
    }
    if (tid == T - 1) g_rowptr[NN] = sh[T - 1];
}

// ---------------- scatter into CSR, 4 edges/thread ----------------------
__global__ void k_scatter(const void* __restrict__ raw, int E) {
    int base = (blockIdx.x * blockDim.x + threadIdx.x) * 4;
    if (g_flag) {
        const long long* p = (const long long*)raw;
#pragma unroll
        for (int u = 0; u < 4; u++) {
            int j = base + u;
            if (j < E) {
                int s = (int)p[j], d = (int)p[E + j];
                int pos = atomicAdd(&g_fill[d], 1);
                g_srcs16[pos] = (unsigned short)s;
            }
        }
    } else {
        const int* p = (const int*)raw;
#pragma unroll
        for (int u = 0; u < 4; u++) {
            int j = base + u;
            if (j < E) {
                int s = p[j], d = p[E + j];
                int pos = atomicAdd(&g_fill[d], 1);
                g_srcs16[pos] = (unsigned short)s;
            }
        }
    }
}

// ---------------- bf16 helpers ----------------
__device__ __forceinline__ void split_bf16(float v, unsigned short& hi, unsigned short& lo) {
    __nv_bfloat16 h = __float2bfloat16(v);
    float r = v - __bfloat162float(h);
    __nv_bfloat16 l = __float2bfloat16(r);
    hi = *reinterpret_cast<unsigned short*>(&h);
    lo = *reinterpret_cast<unsigned short*>(&l);
}

__device__ __forceinline__ void mma16816(float* c, const uint32_t* a, const uint32_t* b) {
    asm volatile(
        "mma.sync.aligned.m16n8k16.row.col.f32.bf16.bf16.f32 "
        "{%0,%1,%2,%3}, {%4,%5,%6,%7}, {%8,%9}, {%0,%1,%2,%3};"
        : "+f"(c[0]), "+f"(c[1]), "+f"(c[2]), "+f"(c[3])
        : "r"(a[0]), "r"(a[1]), "r"(a[2]), "r"(a[3]), "r"(b[0]), "r"(b[1]));
}

// ---------------- tensor-core GEMM (bf16 3-term split) -------------------
// h = x @ W. 96 threads (3 warps), each warp: 2 m16 tiles x 8 n8 tiles.
// A and W split into bf16 hi+lo; acc += Ah*Bh + Ah*Bl + Al*Bh (err ~2^-16).
// Fused epilogue: h -> fp16, s_src/s_dst projections in fp32.
__global__ void __launch_bounds__(96) k_gemm(
        const float* __restrict__ xext, int use_ext,
        const float* __restrict__ W,
        const float* __restrict__ a_s,
        const float* __restrict__ a_d) {
    __shared__ unsigned short Ah[BR][72], Al[BR][72];   // 13824 B each
    __shared__ unsigned short Bh[DD][72], Bl[DD][72];   //  9216 B each
    const float* x = use_ext ? xext : g_buf;
    int t = threadIdx.x;
    int rb = blockIdx.x * BR;

    // stage W transposed (Bh/Bl[c][k] = split(W[k][c]))
    for (int i = t; i < DD * DD; i += 96) {
        int k = i >> 6, c = i & 63;
        unsigned short hi, lo;
        split_bf16(W[i], hi, lo);
        Bh[c][k] = hi; Bl[c][k] = lo;
    }
    // stage x tile rows rb..rb+95
    for (int i = t; i < BR * DD; i += 96) {
        int r = i >> 6, c = i & 63;
        int gr = rb + r; if (gr >= NN) gr = 0;
        unsigned short hi, lo;
        split_bf16(x[(size_t)gr * DD + c], hi, lo);
        Ah[r][c] = hi; Al[r][c] = lo;
    }
    __syncthreads();

    int lane = t & 31, wid = t >> 5;
    int gid = lane >> 2, tig = lane & 3;

    float acc[2][8][4];
#pragma unroll
    for (int mt = 0; mt < 2; mt++)
#pragma unroll
        for (int nt = 0; nt < 8; nt++)
#pragma unroll
            for (int q = 0; q < 4; q++) acc[mt][nt][q] = 0.f;

#pragma unroll
    for (int ks = 0; ks < 4; ks++) {
        int k0 = ks * 16 + 2 * tig;
        uint32_t ahi[2][4], alo[2][4];
#pragma unroll
        for (int mt = 0; mt < 2; mt++) {
            int r0 = wid * 32 + mt * 16 + gid;
            ahi[mt][0] = *(const uint32_t*)&Ah[r0][k0];
            ahi[mt][1] = *(const uint32_t*)&Ah[r0 + 8][k0];
            ahi[mt][2] = *(const uint32_t*)&Ah[r0][k0 + 8];
            ahi[mt][3] = *(const uint32_t*)&Ah[r0 + 8][k0 + 8];
            alo[mt][0] = *(const uint32_t*)&Al[r0][k0];
            alo[mt][1] = *(const uint32_t*)&Al[r0 + 8][k0];
            alo[mt][2] = *(const uint32_t*)&Al[r0][k0 + 8];
            alo[mt][3] = *(const uint32_t*)&Al[r0 + 8][k0 + 8];
        }
#pragma unroll
        for (int nt = 0; nt < 8; nt++) {
            int n = nt * 8 + gid;
            uint32_t bhi[2], blo[2];
            bhi[0] = *(const uint32_t*)&Bh[n][k0];
            bhi[1] = *(const uint32_t*)&Bh[n][k0 + 8];
            blo[0] = *(const uint32_t*)&Bl[n][k0];
            blo[1] = *(const uint32_t*)&Bl[n][k0 + 8];
#pragma unroll
            for (int mt = 0; mt < 2; mt++) {
                mma16816(acc[mt][nt], ahi[mt], bhi);
                mma16816(acc[mt][nt], ahi[mt], blo);
                mma16816(acc[mt][nt], alo[mt], bhi);
            }
        }
    }

    // epilogue
    float2 asv[8], adv[8];
#pragma unroll
    for (int nt = 0; nt < 8; nt++) {
        asv[nt] = ((const float2*)a_s)[nt * 4 + tig];
        adv[nt] = ((const float2*)a_d)[nt * 4 + tig];
    }
#pragma unroll
    for (int mt = 0; mt < 2; mt++) {
        int r0 = rb + wid * 32 + mt * 16 + gid;   // rows r0 and r0+8
        float ss0 = 0.f, sd0 = 0.f, ss1 = 0.f, sd1 = 0.f;
#pragma unroll
        for (int nt = 0; nt < 8; nt++) {
            ss0 = fmaf(acc[mt][nt][0], asv[nt].x, fmaf(acc[mt][nt][1], asv[nt].y, ss0));
            sd0 = fmaf(acc[mt][nt][0], adv[nt].x, fmaf(acc[mt][nt][1], adv[nt].y, sd0));
            ss1 = fmaf(acc[mt][nt][2], asv[nt].x, fmaf(acc[mt][nt][3], asv[nt].y, ss1));
            sd1 = fmaf(acc[mt][nt][2], adv[nt].x, fmaf(acc[mt][nt][3], adv[nt].y, sd1));
        }
#pragma unroll
        for (int o = 1; o <= 2; o <<= 1) {
            ss0 += __shfl_xor_sync(0xffffffffu, ss0, o);
            sd0 += __shfl_xor_sync(0xffffffffu, sd0, o);
            ss1 += __shfl_xor_sync(0xffffffffu, ss1, o);
            sd1 += __shfl_xor_sync(0xffffffffu, sd1, o);
        }
        bool ok0 = (r0 < NN), ok1 = (r0 + 8 < NN);
#pragma unroll
        for (int nt = 0; nt < 8; nt++) {
            int col = nt * 8 + 2 * tig;
            if (ok0)
                *(__half2*)(g_hh + (size_t)r0 * DD + col) =
                    __floats2half2_rn(acc[mt][nt][0], acc[mt][nt][1]);
            if (ok1)
                *(__half2*)(g_hh + (size_t)(r0 + 8) * DD + col) =
                    __floats2half2_rn(acc[mt][nt][2], acc[mt][nt][3]);
        }
        if (tig == 0) {
            if (ok0) { g_ssrc[r0] = ss0; g_sdst[r0] = sd0; }
            if (ok1) { g_ssrc[r0 + 8] = ss1; g_sdst[r0 + 8] = sd1; }
        }
    }
}

// ---------------- per-dst softmax (online) + aggregation (R4 version) ----
__global__ void k_agg(float* __restrict__ yext, int use_ext, int do_elu) {
    int w = (blockIdx.x * blockDim.x + threadIdx.x) >> 5;
    int lane = threadIdx.x & 31;
    if (w >= NN) return;
    float* y = use_ext ? yext : g_buf;
    int start = g_rowptr[w], end = g_rowptr[w + 1];
    float sd = g_sdst[w];

    float m = -1e30f, z = 0.f;
    for (int j = start + lane; j < end; j += 32) {
        float e = g_ssrc[g_srcs16[j]] + sd;
        e = (e > 0.f) ? e : 0.2f * e;
        if (e > m) { z *= __expf(m - e); m = e; }
        z += __expf(e - m);
    }
    float M = m;
#pragma unroll
    for (int o = 16; o; o >>= 1) M = fmaxf(M, __shfl_xor_sync(0xffffffffu, M, o));
    z *= __expf(m - M);
#pragma unroll
    for (int o = 16; o; o >>= 1) z += __shfl_xor_sync(0xffffffffu, z, o);
    float inv = 1.f / (z + 1e-16f);

    int half = lane >> 4, l16 = lane & 15;
    float4 acc = make_float4(0.f, 0.f, 0.f, 0.f);
    const uint2* h8 = (const uint2*)g_hh;
    for (int j = start + half; j < end; j += 2) {
        int s = g_srcs16[j];
        float e = g_ssrc[s] + sd;
        e = (e > 0.f) ? e : 0.2f * e;
        float wgt = __expf(e - M) * inv;
        uint2 hv = h8[(size_t)s * 16 + l16];
        float2 f0 = __half22float2(*reinterpret_cast<const __half2*>(&hv.x));
        float2 f1 = __half22float2(*reinterpret_cast<const __half2*>(&hv.y));
        acc.x = fmaf(f0.x, wgt, acc.x);
        acc.y = fmaf(f0.y, wgt, acc.y);
        acc.z = fmaf(f1.x, wgt, acc.z);
        acc.w = fmaf(f1.y, wgt, acc.w);
    }
    acc.x += __shfl_xor_sync(0xffffffffu, acc.x, 16);
    acc.y += __shfl_xor_sync(0xffffffffu, acc.y, 16);
    acc.z += __shfl_xor_sync(0xffffffffu, acc.z, 16);
    acc.w += __shfl_xor_sync(0xffffffffu, acc.w, 16);
    if (half == 0) {
        if (do_elu) {
            acc.x = (acc.x > 0.f) ? acc.x : (__expf(acc.x) - 1.f);
            acc.y = (acc.y > 0.f) ? acc.y : (__expf(acc.y) - 1.f);
            acc.z = (acc.z > 0.f) ? acc.z : (__expf(acc.z) - 1.f);
            acc.w = (acc.w > 0.f) ? acc.w : (__expf(acc.w) - 1.f);
        }
        ((float4*)y)[(size_t)w * 16 + l16] = acc;
    }
}

// ---------------- launch ----------------
extern "C" void kernel_launch(void* const* d_in, const int* in_sizes, int n_in,
                              void* d_out, int out_size) {
    const float* feat  = (const float*)d_in[0];
    const void*  eidx  = d_in[1];
    const float* W1    = (const float*)d_in[2];
    const float* a_s1  = (const float*)d_in[3];
    const float* a_d1  = (const float*)d_in[4];
    const float* W2    = (const float*)d_in[5];
    const float* a_s2  = (const float*)d_in[6];
    const float* a_d2  = (const float*)d_in[7];
    float* out = (float*)d_out;

    int E = in_sizes[1] / 2;

    const int gemm_grid = (NN + BR - 1) / BR;
    const int agg_grid  = (NN * 32 + 255) / 256;

    // CSR prefix (gemm0 slotted at launch index 3 so ncu profiles it)
    k_detect_zero<<<(NN + 1023) / 1024, 1024>>>((const int*)eidx);
    k_hist<<<(E / 4 + 255) / 256, 256>>>(eidx, E);
    k_scan<<<1, 1024>>>();
    k_gemm<<<gemm_grid, 96>>>(feat, 1, W1, a_s1, a_d1);        // launch 3
    k_scatter<<<(E / 4 + 255) / 256, 256>>>(eidx, E);
    k_agg<<<agg_grid, 256>>>(out, 0, 0);                       // head 0, layer 0

    for (int layer = 0; layer < 2; layer++) {
        const float* W  = layer ? W2   : W1;
        const float* as = layer ? a_s2 : a_s1;
        const float* ad = layer ? a_d2 : a_d1;
        for (int head = (layer == 0 ? 1 : 0); head < 4; head++) {
            int last = (layer == 1 && head == 3);
            int eol  = (head == 3);
            k_gemm<<<gemm_grid, 96>>>(g_buf, 0, W + head * DD * DD,
                                      as + head * DD, ad + head * DD);
            k_agg<<<agg_grid, 256>>>(out, last, eol);
        }
    }
}

// round 7
// speedup vs baseline: 1.0864x; 1.0306x over previous
#include <cuda_runtime.h>
#include <cuda_fp16.h>
#include <cuda_bf16.h>
#include <math.h>
#include <stdint.h>

#define NN 50000
#define EE 800000
#define DD 64
#define BR 96    // rows per GEMM block (3 warps x 32 rows)
#define CAP 96   // per-warp smem stash (max in-degree safety; Poisson(16))

// ---------------- device scratch (static, no allocation) ----------------
__device__ int   g_flag;
__device__ int   g_cnt[NN];
__device__ int   g_rowptr[NN + 1];
__device__ int   g_fill[NN];
__device__ unsigned short g_srcs16[EE];
__device__ __align__(16) unsigned short g_xh[NN * DD];   // x hi (bf16 bits)
__device__ __align__(16) unsigned short g_xl[NN * DD];   // x lo (bf16 bits)
__device__ __align__(16) unsigned short g_Wh[8 * DD * DD]; // W^T hi, 8 slots
__device__ __align__(16) unsigned short g_Wl[8 * DD * DD]; // W^T lo
__device__ __align__(16) __half g_hh[NN * DD];           // per-conv h (fp16)
__device__ float g_ssrc[NN];
__device__ float g_sdst[NN];

__device__ __forceinline__ void split_bf16(float v, unsigned short& hi, unsigned short& lo) {
    __nv_bfloat16 h = __float2bfloat16(v);
    float r = v - __bfloat162float(h);
    __nv_bfloat16 l = __float2bfloat16(r);
    hi = *reinterpret_cast<unsigned short*>(&h);
    lo = *reinterpret_cast<unsigned short*>(&l);
}

// ---------------- launch 0: detect dtype + zero counters ----------------
__global__ void k_detect_zero(const int* __restrict__ raw) {
    int i = blockIdx.x * blockDim.x + threadIdx.x;
    if (i < NN) g_cnt[i] = 0;
    if (blockIdx.x == 0) {
        __shared__ int ok;
        if (threadIdx.x == 0) ok = 1;
        __syncthreads();
        for (int j = threadIdx.x; j < 4096; j += blockDim.x)
            if (raw[2 * j + 1] != 0) ok = 0;
        __syncthreads();
        if (threadIdx.x == 0) g_flag = ok;
    }
}

// ---------------- launch 1: convert feat -> split bf16 ------------------
__global__ void k_cvt(const float* __restrict__ feat) {
    int i = blockIdx.x * blockDim.x + threadIdx.x;
    if (i >= NN * DD) return;
    split_bf16(feat[i], g_xh[i], g_xl[i]);
}

// ---------------- launch 2: split + transpose all 8 W matrices ----------
__global__ void k_cvtW(const float* __restrict__ W1, const float* __restrict__ W2) {
    int i = blockIdx.x * blockDim.x + threadIdx.x;
    if (i >= 8 * DD * DD) return;
    int g = i >> 12;
    int idx = i & 4095;
    int k = idx >> 6, c = idx & 63;
    const float* W = (g < 4) ? W1 : W2;
    float v = W[(g & 3) * DD * DD + k * DD + c];
    split_bf16(v, g_Wh[g * DD * DD + c * DD + k], g_Wl[g * DD * DD + c * DD + k]);
}

// ---------------- tensor-core GEMM (copy-only staging) ------------------
// h = x @ W. 3 warps; warp: 2 m16 tiles x 8 n8 tiles; 3-term bf16 split.
__global__ void __launch_bounds__(96) k_gemm(
        int g, const float* __restrict__ a_s, const float* __restrict__ a_d) {
    __shared__ __align__(16) unsigned short Ah[BR][72], Al[BR][72];
    __shared__ __align__(16) unsigned short Bh[DD][72], Bl[DD][72];
    int t = threadIdx.x;
    int rb = blockIdx.x * BR;

    // stage W^T (hi/lo): 64 rows x 8 uint4
    for (int i = t; i < 512; i += 96) {
        int c = i >> 3, q = i & 7;
        ((uint4*)&Bh[c][0])[q] = ((const uint4*)(g_Wh + g * DD * DD + c * DD))[q];
        ((uint4*)&Bl[c][0])[q] = ((const uint4*)(g_Wl + g * DD * DD + c * DD))[q];
    }
    // stage x tile: 96 rows x 8 uint4
    for (int i = t; i < 768; i += 96) {
        int r = i >> 3, q = i & 7;
        int gr = rb + r; if (gr >= NN) gr = 0;
        ((uint4*)&Ah[r][0])[q] = ((const uint4*)(g_xh + (size_t)gr * DD))[q];
        ((uint4*)&Al[r][0])[q] = ((const uint4*)(g_xl + (size_t)gr * DD))[q];
    }
    __syncthreads();

    int lane = t & 31, wid = t >> 5;
    int gid = lane >> 2, tig = lane & 3;

    float acc[2][8][4];
#pragma unroll
    for (int mt = 0; mt < 2; mt++)
#pragma unroll
        for (int nt = 0; nt < 8; nt++)
#pragma unroll
            for (int q = 0; q < 4; q++) acc[mt][nt][q] = 0.f;

#pragma unroll
    for (int ks = 0; ks < 4; ks++) {
        int k0 = ks * 16 + 2 * tig;
        uint32_t ahi[2][4], alo[2][4];
#pragma unroll
        for (int mt = 0; mt < 2; mt++) {
            int r0 = wid * 32 + mt * 16 + gid;
            ahi[mt][0] = *(const uint32_t*)&Ah[r0][k0];
            ahi[mt][1] = *(const uint32_t*)&Ah[r0 + 8][k0];
            ahi[mt][2] = *(const uint32_t*)&Ah[r0][k0 + 8];
            ahi[mt][3] = *(const uint32_t*)&Ah[r0 + 8][k0 + 8];
            alo[mt][0] = *(const uint32_t*)&Al[r0][k0];
            alo[mt][1] = *(const uint32_t*)&Al[r0 + 8][k0];
            alo[mt][2] = *(const uint32_t*)&Al[r0][k0 + 8];
            alo[mt][3] = *(const uint32_t*)&Al[r0 + 8][k0 + 8];
        }
#pragma unroll
        for (int nt = 0; nt < 8; nt++) {
            int n = nt * 8 + gid;
            uint32_t bhi[2], blo[2];
            bhi[0] = *(const uint32_t*)&Bh[n][k0];
            bhi[1] = *(const uint32_t*)&Bh[n][k0 + 8];
            blo[0] = *(const uint32_t*)&Bl[n][k0];
            blo[1] = *(const uint32_t*)&Bl[n][k0 + 8];
#pragma unroll
            for (int mt = 0; mt < 2; mt++) {
                asm volatile(
                    "mma.sync.aligned.m16n8k16.row.col.f32.bf16.bf16.f32 "
                    "{%0,%1,%2,%3}, {%4,%5,%6,%7}, {%8,%9}, {%0,%1,%2,%3};"
                    : "+f"(acc[mt][nt][0]), "+f"(acc[mt][nt][1]),
                      "+f"(acc[mt][nt][2]), "+f"(acc[mt][nt][3])
                    : "r"(ahi[mt][0]), "r"(ahi[mt][1]), "r"(ahi[mt][2]), "r"(ahi[mt][3]),
                      "r"(bhi[0]), "r"(bhi[1]));
                asm volatile(
                    "mma.sync.aligned.m16n8k16.row.col.f32.bf16.bf16.f32 "
                    "{%0,%1,%2,%3}, {%4,%5,%6,%7}, {%8,%9}, {%0,%1,%2,%3};"
                    : "+f"(acc[mt][nt][0]), "+f"(acc[mt][nt][1]),
                      "+f"(acc[mt][nt][2]), "+f"(acc[mt][nt][3])
                    : "r"(ahi[mt][0]), "r"(ahi[mt][1]), "r"(ahi[mt][2]), "r"(ahi[mt][3]),
                      "r"(blo[0]), "r"(blo[1]));
                asm volatile(
                    "mma.sync.aligned.m16n8k16.row.col.f32.bf16.bf16.f32 "
                    "{%0,%1,%2,%3}, {%4,%5,%6,%7}, {%8,%9}, {%0,%1,%2,%3};"
                    : "+f"(acc[mt][nt][0]), "+f"(acc[mt][nt][1]),
                      "+f"(acc[mt][nt][2]), "+f"(acc[mt][nt][3])
                    : "r"(alo[mt][0]), "r"(alo[mt][1]), "r"(alo[mt][2]), "r"(alo[mt][3]),
                      "r"(bhi[0]), "r"(bhi[1]));
            }
        }
    }

    // epilogue: h -> fp16, fused score projections
    float2 asv[8], adv[8];
#pragma unroll
    for (int nt = 0; nt < 8; nt++) {
        asv[nt] = ((const float2*)a_s)[nt * 4 + tig];
        adv[nt] = ((const float2*)a_d)[nt * 4 + tig];
    }
#pragma unroll
    for (int mt = 0; mt < 2; mt++) {
        int r0 = rb + wid * 32 + mt * 16 + gid;
        float ss0 = 0.f, sd0 = 0.f, ss1 = 0.f, sd1 = 0.f;
#pragma unroll
        for (int nt = 0; nt < 8; nt++) {
            ss0 = fmaf(acc[mt][nt][0], asv[nt].x, fmaf(acc[mt][nt][1], asv[nt].y, ss0));
            sd0 = fmaf(acc[mt][nt][0], adv[nt].x, fmaf(acc[mt][nt][1], adv[nt].y, sd0));
            ss1 = fmaf(acc[mt][nt][2], asv[nt].x, fmaf(acc[mt][nt][3], asv[nt].y, ss1));
            sd1 = fmaf(acc[mt][nt][2], adv[nt].x, fmaf(acc[mt][nt][3], adv[nt].y, sd1));
        }
#pragma unroll
        for (int o = 1; o <= 2; o <<= 1) {
            ss0 += __shfl_xor_sync(0xffffffffu, ss0, o);
            sd0 += __shfl_xor_sync(0xffffffffu, sd0, o);
            ss1 += __shfl_xor_sync(0xffffffffu, ss1, o);
            sd1 += __shfl_xor_sync(0xffffffffu, sd1, o);
        }
        bool ok0 = (r0 < NN), ok1 = (r0 + 8 < NN);
#pragma unroll
        for (int nt = 0; nt < 8; nt++) {
            int col = nt * 8 + 2 * tig;
            if (ok0)
                *(__half2*)(g_hh + (size_t)r0 * DD + col) =
                    __floats2half2_rn(acc[mt][nt][0], acc[mt][nt][1]);
            if (ok1)
                *(__half2*)(g_hh + (size_t)(r0 + 8) * DD + col) =
                    __floats2half2_rn(acc[mt][nt][2], acc[mt][nt][3]);
        }
        if (tig == 0) {
            if (ok0) { g_ssrc[r0] = ss0; g_sdst[r0] = sd0; }
            if (ok1) { g_ssrc[r0 + 8] = ss1; g_sdst[r0 + 8] = sd1; }
        }
    }
}

// ---------------- histogram / scan / scatter ----------------------------
__global__ void k_hist(const void* __restrict__ raw, int E) {
    int base = (blockIdx.x * blockDim.x + threadIdx.x) * 4;
    if (g_flag) {
        const long long* p = (const long long*)raw + E;
#pragma unroll
        for (int u = 0; u < 4; u++) { int j = base + u; if (j < E) atomicAdd(&g_cnt[(int)p[j]], 1); }
    } else {
        const int* p = (const int*)raw + E;
#pragma unroll
        for (int u = 0; u < 4; u++) { int j = base + u; if (j < E) atomicAdd(&g_cnt[p[j]], 1); }
    }
}

__global__ void k_scan() {
    const int T = 1024;
    const int CH = (NN + T - 1) / T;
    __shared__ int sh[T];
    int tid = threadIdx.x;
    int begin = tid * CH;
    int end = begin + CH; if (end > NN) end = NN;
    if (begin > NN) begin = NN;
    int s = 0;
    for (int i = begin; i < end; i++) s += g_cnt[i];
    sh[tid] = s;
    __syncthreads();
    for (int off = 1; off < T; off <<= 1) {
        int v = (tid >= off) ? sh[tid - off] : 0;
        __syncthreads();
        sh[tid] += v;
        __syncthreads();
    }
    int run = sh[tid] - s;
    for (int i = begin; i < end; i++) {
        g_rowptr[i] = run;
        g_fill[i] = run;
        run += g_cnt[i];
    }
    if (tid == T - 1) g_rowptr[NN] = sh[T - 1];
}

__global__ void k_scatter(const void* __restrict__ raw, int E) {
    int base = (blockIdx.x * blockDim.x + threadIdx.x) * 4;
    if (g_flag) {
        const long long* p = (const long long*)raw;
#pragma unroll
        for (int u = 0; u < 4; u++) {
            int j = base + u;
            if (j < E) {
                int pos = atomicAdd(&g_fill[(int)p[E + j]], 1);
                g_srcs16[pos] = (unsigned short)(int)p[j];
            }
        }
    } else {
        const int* p = (const int*)raw;
#pragma unroll
        for (int u = 0; u < 4; u++) {
            int j = base + u;
            if (j < E) {
                int pos = atomicAdd(&g_fill[p[E + j]], 1);
                g_srcs16[pos] = (unsigned short)p[j];
            }
        }
    }
}

// ---------------- per-dst softmax (no max-sub, 1 exp/edge) + agg --------
// One warp per dst node, 8 warps/block. Pass A stashes p=exp(e) and src.
// Output: intermediate convs -> split bf16 (g_xh/g_xl), last -> fp32 d_out.
__global__ void __launch_bounds__(256) k_agg(float* __restrict__ yext,
                                             int is_last, int do_elu) {
    __shared__ float sp[8][CAP];
    __shared__ unsigned short ssv[8][CAP];
    int wib = threadIdx.x >> 5;
    int w = (blockIdx.x * blockDim.x + threadIdx.x) >> 5;
    int lane = threadIdx.x & 31;
    if (w >= NN) return;
    int start = g_rowptr[w], end = g_rowptr[w + 1];
    float sd = g_sdst[w];

    // pass A: z = sum exp(leaky(e)) — softmax shift-invariance, e is O(10)
    float z = 0.f;
    for (int j = start + lane; j < end; j += 32) {
        unsigned short s = g_srcs16[j];
        float e = g_ssrc[s] + sd;
        e = (e > 0.f) ? e : 0.2f * e;
        e = fminf(e, 60.f);
        float p = __expf(e);
        int idx = j - start;
        if (idx < CAP) { sp[wib][idx] = p; ssv[wib][idx] = s; }
        z += p;
    }
#pragma unroll
    for (int o = 16; o; o >>= 1) z += __shfl_xor_sync(0xffffffffu, z, o);
    float inv = 1.f / (z + 1e-16f);
    __syncwarp();

    // pass B: two half-warps, 2 edges/iter; p and s from smem
    int half = lane >> 4, l16 = lane & 15;
    float4 acc = make_float4(0.f, 0.f, 0.f, 0.f);
    const uint2* h8 = (const uint2*)g_hh;
    for (int j = start + half; j < end; j += 2) {
        int idx = j - start;
        int s; float p;
        if (idx < CAP) { s = ssv[wib][idx]; p = sp[wib][idx]; }
        else {
            s = g_srcs16[j];
            float e = g_ssrc[s] + sd;
            e = (e > 0.f) ? e : 0.2f * e;
            p = __expf(fminf(e, 60.f));
        }
        float wgt = p * inv;
        uint2 hv = h8[(size_t)s * 16 + l16];
        float2 f0 = __half22float2(*reinterpret_cast<const __half2*>(&hv.x));
        float2 f1 = __half22float2(*reinterpret_cast<const __half2*>(&hv.y));
        acc.x = fmaf(f0.x, wgt, acc.x);
        acc.y = fmaf(f0.y, wgt, acc.y);
        acc.z = fmaf(f1.x, wgt, acc.z);
        acc.w = fmaf(f1.y, wgt, acc.w);
    }
    acc.x += __shfl_xor_sync(0xffffffffu, acc.x, 16);
    acc.y += __shfl_xor_sync(0xffffffffu, acc.y, 16);
    acc.z += __shfl_xor_sync(0xffffffffu, acc.z, 16);
    acc.w += __shfl_xor_sync(0xffffffffu, acc.w, 16);
    if (half == 0) {
        if (do_elu) {
            acc.x = (acc.x > 0.f) ? acc.x : (__expf(acc.x) - 1.f);
            acc.y = (acc.y > 0.f) ? acc.y : (__expf(acc.y) - 1.f);
            acc.z = (acc.z > 0.f) ? acc.z : (__expf(acc.z) - 1.f);
            acc.w = (acc.w > 0.f) ? acc.w : (__expf(acc.w) - 1.f);
        }
        if (is_last) {
            ((float4*)yext)[(size_t)w * 16 + l16] = acc;
        } else {
            ushort4 hh, ll;
            split_bf16(acc.x, hh.x, ll.x);
            split_bf16(acc.y, hh.y, ll.y);
            split_bf16(acc.z, hh.z, ll.z);
            split_bf16(acc.w, hh.w, ll.w);
            *(ushort4*)(g_xh + (size_t)w * DD + l16 * 4) = hh;
            *(ushort4*)(g_xl + (size_t)w * DD + l16 * 4) = ll;
        }
    }
}

// ---------------- launch ----------------
extern "C" void kernel_launch(void* const* d_in, const int* in_sizes, int n_in,
                              void* d_out, int out_size) {
    const float* feat  = (const float*)d_in[0];
    const void*  eidx  = d_in[1];
    const float* W1    = (const float*)d_in[2];
    const float* a_s1  = (const float*)d_in[3];
    const float* a_d1  = (const float*)d_in[4];
    const float* W2    = (const float*)d_in[5];
    const float* a_s2  = (const float*)d_in[6];
    const float* a_d2  = (const float*)d_in[7];
    float* out = (float*)d_out;

    int E = in_sizes[1] / 2;

    const int gemm_grid = (NN + BR - 1) / BR;
    const int agg_grid  = (NN * 32 + 255) / 256;

    k_detect_zero<<<(NN + 1023) / 1024, 1024>>>((const int*)eidx);   // 0
    k_cvt<<<(NN * DD + 255) / 256, 256>>>(feat);                     // 1
    k_cvtW<<<(8 * DD * DD + 255) / 256, 256>>>(W1, W2);              // 2
    k_gemm<<<gemm_grid, 96>>>(0, a_s1, a_d1);                        // 3 (profiled)
    k_hist<<<(E / 4 + 255) / 256, 256>>>(eidx, E);                   // 4
    k_scan<<<1, 1024>>>();                                           // 5
    k_scatter<<<(E / 4 + 255) / 256, 256>>>(eidx, E);                // 6
    k_agg<<<agg_grid, 256>>>(out, 0, 0);                             // 7

    for (int layer = 0; layer < 2; layer++) {
        const float* as = layer ? a_s2 : a_s1;
        const float* ad = layer ? a_d2 : a_d1;
        for (int head = (layer == 0 ? 1 : 0); head < 4; head++) {
            int g = layer * 4 + head;
            int last = (layer == 1 && head == 3);
            int eol  = (head == 3);
            k_gemm<<<gemm_grid, 96>>>(g, as + head * DD, ad + head * DD);
            k_agg<<<agg_grid, 256>>>(out, last, eol);
        }
    }
}

// round 8
// speedup vs baseline: 1.1439x; 1.0529x over previous
#include <cuda_runtime.h>
#include <cuda_fp16.h>
#include <cuda_bf16.h>
#include <math.h>
#include <stdint.h>

#define NN 50000
#define EE 800000
#define DD 64
#define BR 128   // rows per GEMM block (8 warps x 16 rows)
#define CAP 96   // per-warp smem stash (max in-degree safety; Poisson(16))

// ---------------- device scratch (static, no allocation) ----------------
__device__ int   g_flag;
__device__ int   g_cnt[NN];
__device__ int   g_rowptr[NN + 1];
__device__ int   g_fill[NN];
__device__ unsigned short g_srcs16[EE];
__device__ __align__(16) unsigned short g_xh[NN * DD];     // x hi (bf16 bits)
__device__ __align__(16) unsigned short g_xl[NN * DD];     // x lo (bf16 bits)
__device__ __align__(16) unsigned short g_Wh[8 * DD * DD]; // W^T hi, 8 slots
__device__ __align__(16) unsigned short g_Wl[8 * DD * DD]; // W^T lo
__device__ __align__(16) __half g_hh[NN * DD];             // per-conv h (fp16)
__device__ float g_ssrc[NN];
__device__ float g_sdst[NN];

__device__ __forceinline__ void split_bf16(float v, unsigned short& hi, unsigned short& lo) {
    __nv_bfloat16 h = __float2bfloat16(v);
    float r = v - __bfloat162float(h);
    __nv_bfloat16 l = __float2bfloat16(r);
    hi = *reinterpret_cast<unsigned short*>(&h);
    lo = *reinterpret_cast<unsigned short*>(&l);
}

// ---------------- launch 0: init (detect + zero + cvt feat + cvt W) -----
__global__ void k_init(const int* __restrict__ raw,
                       const float* __restrict__ feat,
                       const float* __restrict__ W1,
                       const float* __restrict__ W2) {
    int i = blockIdx.x * blockDim.x + threadIdx.x;
    if (i < NN * DD) split_bf16(feat[i], g_xh[i], g_xl[i]);
    if (i < NN) g_cnt[i] = 0;
    if (i < 8 * DD * DD) {
        int g = i >> 12;
        int idx = i & 4095;
        int k = idx >> 6, c = idx & 63;
        const float* W = (g < 4) ? W1 : W2;
        float v = W[(g & 3) * DD * DD + k * DD + c];
        split_bf16(v, g_Wh[g * DD * DD + c * DD + k], g_Wl[g * DD * DD + c * DD + k]);
    }
    if (blockIdx.x == 0) {
        __shared__ int ok;
        if (threadIdx.x == 0) ok = 1;
        __syncthreads();
        for (int j = threadIdx.x; j < 4096; j += blockDim.x)
            if (raw[2 * j + 1] != 0) ok = 0;
        __syncthreads();
        if (threadIdx.x == 0) g_flag = ok;
    }
}

// ---------------- tensor-core GEMM (8 warps, dynamic smem) --------------
// h = x @ W. 256 threads; warp w: rows rb+16w..+16 (one m16 tile) x 8 n-tiles.
// 3-term bf16 split (err ~2^-16). Fused fp16-h store + score projections.
__global__ void __launch_bounds__(256) k_gemm(
        int g, const float* __restrict__ a_s, const float* __restrict__ a_d) {
    extern __shared__ __align__(16) char smem[];
    unsigned short (*Ah)[72] = (unsigned short(*)[72])(smem);
    unsigned short (*Al)[72] = (unsigned short(*)[72])(smem + 18432);
    unsigned short (*Bh)[72] = (unsigned short(*)[72])(smem + 36864);
    unsigned short (*Bl)[72] = (unsigned short(*)[72])(smem + 46080);
    int t = threadIdx.x;
    int rb = blockIdx.x * BR;

    // stage W^T hi/lo: 64 rows x 8 uint4 each
    for (int i = t; i < 512; i += 256) {
        int c = i >> 3, q = i & 7;
        ((uint4*)&Bh[c][0])[q] = ((const uint4*)(g_Wh + g * DD * DD + c * DD))[q];
        ((uint4*)&Bl[c][0])[q] = ((const uint4*)(g_Wl + g * DD * DD + c * DD))[q];
    }
    // stage x tile: 128 rows x 8 uint4 each
    for (int i = t; i < 1024; i += 256) {
        int r = i >> 3, q = i & 7;
        int gr = rb + r; if (gr >= NN) gr = 0;
        ((uint4*)&Ah[r][0])[q] = ((const uint4*)(g_xh + (size_t)gr * DD))[q];
        ((uint4*)&Al[r][0])[q] = ((const uint4*)(g_xl + (size_t)gr * DD))[q];
    }
    __syncthreads();

    int lane = t & 31, wid = t >> 5;
    int gid = lane >> 2, tig = lane & 3;

    float acc[8][4];
#pragma unroll
    for (int nt = 0; nt < 8; nt++)
#pragma unroll
        for (int q = 0; q < 4; q++) acc[nt][q] = 0.f;

#pragma unroll
    for (int ks = 0; ks < 4; ks++) {
        int k0 = ks * 16 + 2 * tig;
        int r0 = wid * 16 + gid;
        uint32_t ahi[4], alo[4];
        ahi[0] = *(const uint32_t*)&Ah[r0][k0];
        ahi[1] = *(const uint32_t*)&Ah[r0 + 8][k0];
        ahi[2] = *(const uint32_t*)&Ah[r0][k0 + 8];
        ahi[3] = *(const uint32_t*)&Ah[r0 + 8][k0 + 8];
        alo[0] = *(const uint32_t*)&Al[r0][k0];
        alo[1] = *(const uint32_t*)&Al[r0 + 8][k0];
        alo[2] = *(const uint32_t*)&Al[r0][k0 + 8];
        alo[3] = *(const uint32_t*)&Al[r0 + 8][k0 + 8];
#pragma unroll
        for (int nt = 0; nt < 8; nt++) {
            int n = nt * 8 + gid;
            uint32_t bhi[2], blo[2];
            bhi[0] = *(const uint32_t*)&Bh[n][k0];
            bhi[1] = *(const uint32_t*)&Bh[n][k0 + 8];
            blo[0] = *(const uint32_t*)&Bl[n][k0];
            blo[1] = *(const uint32_t*)&Bl[n][k0 + 8];
            asm volatile(
                "mma.sync.aligned.m16n8k16.row.col.f32.bf16.bf16.f32 "
                "{%0,%1,%2,%3}, {%4,%5,%6,%7}, {%8,%9}, {%0,%1,%2,%3};"
                : "+f"(acc[nt][0]), "+f"(acc[nt][1]), "+f"(acc[nt][2]), "+f"(acc[nt][3])
                : "r"(ahi[0]), "r"(ahi[1]), "r"(ahi[2]), "r"(ahi[3]),
                  "r"(bhi[0]), "r"(bhi[1]));
            asm volatile(
                "mma.sync.aligned.m16n8k16.row.col.f32.bf16.bf16.f32 "
                "{%0,%1,%2,%3}, {%4,%5,%6,%7}, {%8,%9}, {%0,%1,%2,%3};"
                : "+f"(acc[nt][0]), "+f"(acc[nt][1]), "+f"(acc[nt][2]), "+f"(acc[nt][3])
                : "r"(ahi[0]), "r"(ahi[1]), "r"(ahi[2]), "r"(ahi[3]),
                  "r"(blo[0]), "r"(blo[1]));
            asm volatile(
                "mma.sync.aligned.m16n8k16.row.col.f32.bf16.bf16.f32 "
                "{%0,%1,%2,%3}, {%4,%5,%6,%7}, {%8,%9}, {%0,%1,%2,%3};"
                : "+f"(acc[nt][0]), "+f"(acc[nt][1]), "+f"(acc[nt][2]), "+f"(acc[nt][3])
                : "r"(alo[0]), "r"(alo[1]), "r"(alo[2]), "r"(alo[3]),
                  "r"(bhi[0]), "r"(bhi[1]));
        }
    }

    // epilogue
    float2 asv[8], adv[8];
#pragma unroll
    for (int nt = 0; nt < 8; nt++) {
        asv[nt] = ((const float2*)a_s)[nt * 4 + tig];
        adv[nt] = ((const float2*)a_d)[nt * 4 + tig];
    }
    int r0 = rb + wid * 16 + gid;   // rows r0 and r0+8
    float ss0 = 0.f, sd0 = 0.f, ss1 = 0.f, sd1 = 0.f;
#pragma unroll
    for (int nt = 0; nt < 8; nt++) {
        ss0 = fmaf(acc[nt][0], asv[nt].x, fmaf(acc[nt][1], asv[nt].y, ss0));
        sd0 = fmaf(acc[nt][0], adv[nt].x, fmaf(acc[nt][1], adv[nt].y, sd0));
        ss1 = fmaf(acc[nt][2], asv[nt].x, fmaf(acc[nt][3], asv[nt].y, ss1));
        sd1 = fmaf(acc[nt][2], adv[nt].x, fmaf(acc[nt][3], adv[nt].y, sd1));
    }
#pragma unroll
    for (int o = 1; o <= 2; o <<= 1) {
        ss0 += __shfl_xor_sync(0xffffffffu, ss0, o);
        sd0 += __shfl_xor_sync(0xffffffffu, sd0, o);
        ss1 += __shfl_xor_sync(0xffffffffu, ss1, o);
        sd1 += __shfl_xor_sync(0xffffffffu, sd1, o);
    }
    bool ok0 = (r0 < NN), ok1 = (r0 + 8 < NN);
#pragma unroll
    for (int nt = 0; nt < 8; nt++) {
        int col = nt * 8 + 2 * tig;
        if (ok0)
            *(__half2*)(g_hh + (size_t)r0 * DD + col) =
                __floats2half2_rn(acc[nt][0], acc[nt][1]);
        if (ok1)
            *(__half2*)(g_hh + (size_t)(r0 + 8) * DD + col) =
                __floats2half2_rn(acc[nt][2], acc[nt][3]);
    }
    if (tig == 0) {
        if (ok0) { g_ssrc[r0] = ss0; g_sdst[r0] = sd0; }
        if (ok1) { g_ssrc[r0 + 8] = ss1; g_sdst[r0 + 8] = sd1; }
    }
}

// ---------------- histogram / scan / scatter ----------------------------
__global__ void k_hist(const void* __restrict__ raw, int E) {
    int base = (blockIdx.x * blockDim.x + threadIdx.x) * 4;
    if (g_flag) {
        const long long* p = (const long long*)raw + E;
#pragma unroll
        for (int u = 0; u < 4; u++) { int j = base + u; if (j < E) atomicAdd(&g_cnt[(int)p[j]], 1); }
    } else {
        const int* p = (const int*)raw + E;
#pragma unroll
        for (int u = 0; u < 4; u++) { int j = base + u; if (j < E) atomicAdd(&g_cnt[p[j]], 1); }
    }
}

__global__ void k_scan() {
    const int T = 1024;
    const int CH = (NN + T - 1) / T;
    __shared__ int sh[T];
    int tid = threadIdx.x;
    int begin = tid * CH;
    int end = begin + CH; if (end > NN) end = NN;
    if (begin > NN) begin = NN;
    int s = 0;
    for (int i = begin; i < end; i++) s += g_cnt[i];
    sh[tid] = s;
    __syncthreads();
    for (int off = 1; off < T; off <<= 1) {
        int v = (tid >= off) ? sh[tid - off] : 0;
        __syncthreads();
        sh[tid] += v;
        __syncthreads();
    }
    int run = sh[tid] - s;
    for (int i = begin; i < end; i++) {
        g_rowptr[i] = run;
        g_fill[i] = run;
        run += g_cnt[i];
    }
    if (tid == T - 1) g_rowptr[NN] = sh[T - 1];
}

__global__ void k_scatter(const void* __restrict__ raw, int E) {
    int base = (blockIdx.x * blockDim.x + threadIdx.x) * 4;
    if (g_flag) {
        const long long* p = (const long long*)raw;
#pragma unroll
        for (int u = 0; u < 4; u++) {
            int j = base + u;
            if (j < E) {
                int pos = atomicAdd(&g_fill[(int)p[E + j]], 1);
                g_srcs16[pos] = (unsigned short)(int)p[j];
            }
        }
    } else {
        const int* p = (const int*)raw;
#pragma unroll
        for (int u = 0; u < 4; u++) {
            int j = base + u;
            if (j < E) {
                int pos = atomicAdd(&g_fill[p[E + j]], 1);
                g_srcs16[pos] = (unsigned short)p[j];
            }
        }
    }
}

// ---------------- per-dst softmax (1 exp/edge) + aggregation -------------
// One warp per dst node. Pass A stashes p=exp(e). Pass B: quarter-warps,
// 4 edges/iter, uint4 (8 fp16) per lane per edge.
__global__ void __launch_bounds__(256) k_agg(float* __restrict__ yext,
                                             int is_last, int do_elu) {
    __shared__ float sp[8][CAP];
    __shared__ unsigned short ssv[8][CAP];
    int wib = threadIdx.x >> 5;
    int w = (blockIdx.x * blockDim.x + threadIdx.x) >> 5;
    int lane = threadIdx.x & 31;
    if (w >= NN) return;
    int start = g_rowptr[w], end = g_rowptr[w + 1];
    float sd = g_sdst[w];

    // pass A: z = sum exp(leaky(e)); softmax shift-invariance, scores O(10)
    float z = 0.f;
    for (int j = start + lane; j < end; j += 32) {
        unsigned short s = g_srcs16[j];
        float e = g_ssrc[s] + sd;
        e = (e > 0.f) ? e : 0.2f * e;
        e = fminf(e, 60.f);
        float p = __expf(e);
        int idx = j - start;
        if (idx < CAP) { sp[wib][idx] = p; ssv[wib][idx] = s; }
        z += p;
    }
#pragma unroll
    for (int o = 16; o; o >>= 1) z += __shfl_xor_sync(0xffffffffu, z, o);
    float inv = 1.f / (z + 1e-16f);
    __syncwarp();

    // pass B: quarter-warps, 4 edges/iter; p and s from smem
    int q = lane >> 3, l8 = lane & 7;
    float acc[8];
#pragma unroll
    for (int i = 0; i < 8; i++) acc[i] = 0.f;
    const uint4* h16 = (const uint4*)g_hh;   // row = 8 uint4
    for (int j = start + q; j < end; j += 4) {
        int idx = j - start;
        int s; float p;
        if (idx < CAP) { s = ssv[wib][idx]; p = sp[wib][idx]; }
        else {
            s = g_srcs16[j];
            float e = g_ssrc[s] + sd;
            e = (e > 0.f) ? e : 0.2f * e;
            p = __expf(fminf(e, 60.f));
        }
        float wgt = p * inv;
        uint4 hv = h16[(size_t)s * 8 + l8];
        float2 f0 = __half22float2(*reinterpret_cast<const __half2*>(&hv.x));
        float2 f1 = __half22float2(*reinterpret_cast<const __half2*>(&hv.y));
        float2 f2 = __half22float2(*reinterpret_cast<const __half2*>(&hv.z));
        float2 f3 = __half22float2(*reinterpret_cast<const __half2*>(&hv.w));
        acc[0] = fmaf(f0.x, wgt, acc[0]);
        acc[1] = fmaf(f0.y, wgt, acc[1]);
        acc[2] = fmaf(f1.x, wgt, acc[2]);
        acc[3] = fmaf(f1.y, wgt, acc[3]);
        acc[4] = fmaf(f2.x, wgt, acc[4]);
        acc[5] = fmaf(f2.y, wgt, acc[5]);
        acc[6] = fmaf(f3.x, wgt, acc[6]);
        acc[7] = fmaf(f3.y, wgt, acc[7]);
    }
#pragma unroll
    for (int i = 0; i < 8; i++) {
        acc[i] += __shfl_xor_sync(0xffffffffu, acc[i], 8);
        acc[i] += __shfl_xor_sync(0xffffffffu, acc[i], 16);
    }
    if (q == 0) {
        if (do_elu) {
#pragma unroll
            for (int i = 0; i < 8; i++)
                acc[i] = (acc[i] > 0.f) ? acc[i] : (__expf(acc[i]) - 1.f);
        }
        if (is_last) {
            float4 v0 = make_float4(acc[0], acc[1], acc[2], acc[3]);
            float4 v1 = make_float4(acc[4], acc[5], acc[6], acc[7]);
            ((float4*)yext)[(size_t)w * 16 + l8 * 2]     = v0;
            ((float4*)yext)[(size_t)w * 16 + l8 * 2 + 1] = v1;
        } else {
            ushort4 hh0, ll0, hh1, ll1;
            split_bf16(acc[0], hh0.x, ll0.x);
            split_bf16(acc[1], hh0.y, ll0.y);
            split_bf16(acc[2], hh0.z, ll0.z);
            split_bf16(acc[3], hh0.w, ll0.w);
            split_bf16(acc[4], hh1.x, ll1.x);
            split_bf16(acc[5], hh1.y, ll1.y);
            split_bf16(acc[6], hh1.z, ll1.z);
            split_bf16(acc[7], hh1.w, ll1.w);
            *(ushort4*)(g_xh + (size_t)w * DD + l8 * 8)     = hh0;
            *(ushort4*)(g_xh + (size_t)w * DD + l8 * 8 + 4) = hh1;
            *(ushort4*)(g_xl + (size_t)w * DD + l8 * 8)     = ll0;
            *(ushort4*)(g_xl + (size_t)w * DD + l8 * 8 + 4) = ll1;
        }
    }
}

// ---------------- launch ----------------
extern "C" void kernel_launch(void* const* d_in, const int* in_sizes, int n_in,
                              void* d_out, int out_size) {
    const float* feat  = (const float*)d_in[0];
    const void*  eidx  = d_in[1];
    const float* W1    = (const float*)d_in[2];
    const float* a_s1  = (const float*)d_in[3];
    const float* a_d1  = (const float*)d_in[4];
    const float* W2    = (const float*)d_in[5];
    const float* a_s2  = (const float*)d_in[6];
    const float* a_d2  = (const float*)d_in[7];
    float* out = (float*)d_out;

    int E = in_sizes[1] / 2;

    static int smem_set = 0;
    if (!smem_set) {
        cudaFuncSetAttribute(k_gemm, cudaFuncAttributeMaxDynamicSharedMemorySize, 55296);
        smem_set = 1;
    }

    const int gemm_grid = (NN + BR - 1) / BR;
    const int agg_grid  = (NN * 32 + 255) / 256;

    k_init<<<(NN * DD + 255) / 256, 256>>>((const int*)eidx, feat, W1, W2);  // 0
    k_gemm<<<gemm_grid, 256, 55296>>>(0, a_s1, a_d1);                        // 1
    k_hist<<<(E / 4 + 255) / 256, 256>>>(eidx, E);                           // 2
    k_scan<<<1, 1024>>>();                                                   // 3
    k_scatter<<<(E / 4 + 255) / 256, 256>>>(eidx, E);                        // 4
    k_agg<<<agg_grid, 256>>>(out, 0, 0);                                     // 5

    for (int layer = 0; layer < 2; layer++) {
        const float* as = layer ? a_s2 : a_s1;
        const float* ad = layer ? a_d2 : a_d1;
        for (int head = (layer == 0 ? 1 : 0); head < 4; head++) {
            int g = layer * 4 + head;
            int last = (layer == 1 && head == 3);
            int eol  = (head == 3);
            k_gemm<<<gemm_grid, 256, 55296>>>(g, as + head * DD, ad + head * DD);
            k_agg<<<agg_grid, 256>>>(out, last, eol);
        }
    }
}